// round 6
// baseline (speedup 1.0000x reference)
#include <cuda_runtime.h>
#include <cstdint>

#define NMAX 200000
#define EMAX 6400000
#define NB_MAX 1024
#define THREADS 256
#define GT 64   // gemm tile nodes

// Scratch (device globals — no allocation allowed)
__device__ int g_deg[NMAX];
__device__ int g_rowoff[NMAX];
__device__ int g_cursor[NMAX];
__device__ int g_csum[NB_MAX];
__device__ int g_csr[EMAX];
__device__ __align__(16) float g_dinv[NMAX];
__device__ __align__(16) float g_tmpA[NMAX * 4];
__device__ __align__(16) float g_tmpB[NMAX * 4];
__device__ __align__(16) float g_tmpC[NMAX * 2];

// Monotonic ticket barrier — replay-safe (counters only grow; each round
// consumes exactly nb arrivals so ticket%nb stays aligned across graph replays).
__device__ unsigned int g_bar_arrive;
__device__ unsigned int g_bar_release;

__device__ __forceinline__ void grid_barrier(int nb) {
    __syncthreads();
    if (threadIdx.x == 0) {
        __threadfence();
        unsigned int ticket = atomicAdd(&g_bar_arrive, 1u);
        unsigned int target = ticket - (ticket % (unsigned)nb) + (unsigned)nb;
        if ((ticket % (unsigned)nb) == (unsigned)(nb - 1)) {
            atomicAdd(&g_bar_release, (unsigned)nb);
        } else {
            while (atomicAdd(&g_bar_release, 0u) < target) __nanosleep(64);
        }
    }
    __syncthreads();
    __threadfence();
}

__global__ void __launch_bounds__(THREADS, 2)
gcn_mega_kernel(const float* __restrict__ x,
                const float* __restrict__ W1, const float* __restrict__ b1,
                const float* __restrict__ W2, const float* __restrict__ b2,
                const float* __restrict__ W3, const float* __restrict__ b3,
                const float* __restrict__ Wc, const float* __restrict__ bc,
                const int* __restrict__ src, const int* __restrict__ dst,
                float* __restrict__ out, float* __restrict__ hsec,
                int n, int e, int nb) {
    __shared__ union {
        struct { float4 Wv[128]; float4 xs[GT * 33]; float4 ps[GT][4]; } g; // ~40KB
        struct { int wsum[8]; int woff[8]; int red[THREADS]; } s;
    } sm;

    const int t   = threadIdx.x;
    const int blk = blockIdx.x;
    const int gid = blk * THREADS + t;
    const int T   = nb * THREADS;

    // ---- phase 0: zero degree ----
    for (int i = gid; i < n; i += T) __stcg(&g_deg[i], 0);
    grid_barrier(nb);

    // ---- phase 1: count in-degree ----
    {
        int quads = e >> 2;
        for (int q = gid; q < quads; q += T) {
            int4 d4 = __ldg((const int4*)dst + q);
            atomicAdd(&g_deg[d4.x], 1);
            atomicAdd(&g_deg[d4.y], 1);
            atomicAdd(&g_deg[d4.z], 1);
            atomicAdd(&g_deg[d4.w], 1);
        }
        if (gid == 0)
            for (int i = quads * 4; i < e; i++) atomicAdd(&g_deg[dst[i]], 1);
    }
    grid_barrier(nb);

    // ---- phase 2: block-local exclusive scan over this block's node chunk ----
    const int chunk = (n + nb - 1) / nb;
    const int c0 = blk * chunk;
    const int c1 = min(n, c0 + chunk);
    const int per = (chunk + THREADS - 1) / THREADS;
    const int r0 = min(c1, c0 + t * per);
    const int r1 = min(c1, r0 + per);
    {
        int s = 0;
        for (int i = r0; i < r1; i++) s += __ldcg(&g_deg[i]);
        int lane = t & 31, wid = t >> 5;
        int incl = s;
        #pragma unroll
        for (int off = 1; off < 32; off <<= 1) {
            int v = __shfl_up_sync(0xffffffffu, incl, off);
            if (lane >= off) incl += v;
        }
        if (lane == 31) sm.s.wsum[wid] = incl;
        __syncthreads();
        if (t < 8) {
            int acc = 0;
            for (int w = 0; w < t; w++) acc += sm.s.wsum[w];
            sm.s.woff[t] = acc;
        }
        __syncthreads();
        int run = incl - s + sm.s.woff[wid];
        for (int i = r0; i < r1; i++) {
            g_rowoff[i] = run;
            run += __ldcg(&g_deg[i]);
        }
        if (t == 0) __stcg(&g_csum[blk], sm.s.woff[7] + sm.s.wsum[7]);
        __syncthreads();
    }
    grid_barrier(nb);

    // ---- phase 3: apply chunk offsets + dinv + cursor ----
    {
        int p = 0;
        for (int j = t; j < blk; j += THREADS) p += __ldcg(&g_csum[j]);
        sm.s.red[t] = p;
        __syncthreads();
        for (int step = THREADS / 2; step > 0; step >>= 1) {
            if (t < step) sm.s.red[t] += sm.s.red[t + step];
            __syncthreads();
        }
        int off = sm.s.red[0];
        __syncthreads();
        for (int i = r0; i < r1; i++) {
            int v = g_rowoff[i] + off;
            g_rowoff[i] = v;
            g_cursor[i] = v;
            g_dinv[i] = rsqrtf((float)(__ldcg(&g_deg[i]) + 1));  // +1 self-loop
        }
    }
    grid_barrier(nb);

    // ---- phase 4: CSR scatter ----
    {
        int quads = e >> 2;
        for (int q = gid; q < quads; q += T) {
            int4 s4 = __ldg((const int4*)src + q);
            int4 d4 = __ldg((const int4*)dst + q);
            int p;
            p = atomicAdd(&g_cursor[d4.x], 1); __stcg(&g_csr[p], s4.x);
            p = atomicAdd(&g_cursor[d4.y], 1); __stcg(&g_csr[p], s4.y);
            p = atomicAdd(&g_cursor[d4.z], 1); __stcg(&g_csr[p], s4.z);
            p = atomicAdd(&g_cursor[d4.w], 1); __stcg(&g_csr[p], s4.w);
        }
        if (gid == 0)
            for (int i = quads * 4; i < e; i++) {
                int p = atomicAdd(&g_cursor[dst[i]], 1);
                __stcg(&g_csr[p], src[i]);
            }
    }
    grid_barrier(nb);

    // ---- phase 5: layer-1 GEMM tmpA = (x @ W1) * dinv  (smem tile) ----
    {
        if (t < 128) sm.g.Wv[t] = ((const float4*)W1)[t];
        __syncthreads();
        int ntiles = (n + GT - 1) / GT;
        const float4* x4 = (const float4*)x;
        for (int tile = blk; tile < ntiles; tile += nb) {
            int node0 = tile * GT;
            int nn = min(GT, n - node0);
            int tot = nn * 32;
            for (int idx = t; idx < tot; idx += THREADS) {
                int nd = idx >> 5, kq = idx & 31;
                sm.g.xs[nd * 33 + kq] = x4[(size_t)(node0 + nd) * 32 + kq];
            }
            __syncthreads();
            int node = t >> 2, q = t & 3;
            if (node < nn) {
                float4 acc = make_float4(0.f, 0.f, 0.f, 0.f);
                int k0 = q * 8;
                #pragma unroll
                for (int kq = 0; kq < 8; kq++) {
                    float4 xv = sm.g.xs[node * 33 + k0 + kq];
                    float4 w0 = sm.g.Wv[(k0 + kq) * 4 + 0];
                    float4 w1 = sm.g.Wv[(k0 + kq) * 4 + 1];
                    float4 w2 = sm.g.Wv[(k0 + kq) * 4 + 2];
                    float4 w3 = sm.g.Wv[(k0 + kq) * 4 + 3];
                    acc.x += xv.x * w0.x + xv.y * w1.x + xv.z * w2.x + xv.w * w3.x;
                    acc.y += xv.x * w0.y + xv.y * w1.y + xv.z * w2.y + xv.w * w3.y;
                    acc.z += xv.x * w0.z + xv.y * w1.z + xv.z * w2.z + xv.w * w3.z;
                    acc.w += xv.x * w0.w + xv.y * w1.w + xv.z * w2.w + xv.w * w3.w;
                }
                sm.g.ps[node][q] = acc;
            }
            __syncthreads();
            if (t < nn) {
                float4 p0 = sm.g.ps[t][0], p1 = sm.g.ps[t][1];
                float4 p2 = sm.g.ps[t][2], p3 = sm.g.ps[t][3];
                int i = node0 + t;
                float dv = g_dinv[i];
                float4 o = make_float4(((p0.x + p1.x) + (p2.x + p3.x)) * dv,
                                       ((p0.y + p1.y) + (p2.y + p3.y)) * dv,
                                       ((p0.z + p1.z) + (p2.z + p3.z)) * dv,
                                       ((p0.w + p1.w) + (p2.w + p3.w)) * dv);
                *(float4*)(g_tmpA + (size_t)i * 4) = o;
            }
            __syncthreads();
        }
    }
    grid_barrier(nb);

    // ---- phase 6: pull layer 1 (tmpA -> tmpB), fused tanh + GEMM(4->4) + prescale ----
    {
        const float4* tp = (const float4*)g_tmpA;
        for (int i = gid; i < n; i += T) {
            float4 a0 = tp[i];
            float4 a1 = make_float4(0.f, 0.f, 0.f, 0.f), a2 = a1, a3 = a1;
            int j = g_rowoff[i];
            int jend = j + __ldcg(&g_deg[i]);
            for (; j + 4 <= jend; j += 4) {
                int s0 = __ldg(&g_csr[j]),     s1 = __ldg(&g_csr[j + 1]);
                int s2 = __ldg(&g_csr[j + 2]), s3 = __ldg(&g_csr[j + 3]);
                float4 v0 = tp[s0], v1 = tp[s1], v2 = tp[s2], v3 = tp[s3];
                a0.x += v0.x; a0.y += v0.y; a0.z += v0.z; a0.w += v0.w;
                a1.x += v1.x; a1.y += v1.y; a1.z += v1.z; a1.w += v1.w;
                a2.x += v2.x; a2.y += v2.y; a2.z += v2.z; a2.w += v2.w;
                a3.x += v3.x; a3.y += v3.y; a3.z += v3.z; a3.w += v3.w;
            }
            for (; j < jend; j++) {
                float4 v = tp[__ldg(&g_csr[j])];
                a0.x += v.x; a0.y += v.y; a0.z += v.z; a0.w += v.w;
            }
            float dv = g_dinv[i];
            float h0 = tanhf(((a0.x + a1.x) + (a2.x + a3.x)) * dv + __ldg(&b1[0]));
            float h1 = tanhf(((a0.y + a1.y) + (a2.y + a3.y)) * dv + __ldg(&b1[1]));
            float h2 = tanhf(((a0.z + a1.z) + (a2.z + a3.z)) * dv + __ldg(&b1[2]));
            float h3 = tanhf(((a0.w + a1.w) + (a2.w + a3.w)) * dv + __ldg(&b1[3]));
            float4 o;
            o.x = (h0*__ldg(&W2[0]) + h1*__ldg(&W2[4]) + h2*__ldg(&W2[8])  + h3*__ldg(&W2[12])) * dv;
            o.y = (h0*__ldg(&W2[1]) + h1*__ldg(&W2[5]) + h2*__ldg(&W2[9])  + h3*__ldg(&W2[13])) * dv;
            o.z = (h0*__ldg(&W2[2]) + h1*__ldg(&W2[6]) + h2*__ldg(&W2[10]) + h3*__ldg(&W2[14])) * dv;
            o.w = (h0*__ldg(&W2[3]) + h1*__ldg(&W2[7]) + h2*__ldg(&W2[11]) + h3*__ldg(&W2[15])) * dv;
            *(float4*)(g_tmpB + (size_t)i * 4) = o;
        }
    }
    grid_barrier(nb);

    // ---- phase 7: pull layer 2 (tmpB -> tmpC), fused tanh + GEMM(4->2) + prescale ----
    {
        const float4* tp = (const float4*)g_tmpB;
        for (int i = gid; i < n; i += T) {
            float4 a0 = tp[i];
            float4 a1 = make_float4(0.f, 0.f, 0.f, 0.f), a2 = a1, a3 = a1;
            int j = g_rowoff[i];
            int jend = j + __ldcg(&g_deg[i]);
            for (; j + 4 <= jend; j += 4) {
                int s0 = __ldg(&g_csr[j]),     s1 = __ldg(&g_csr[j + 1]);
                int s2 = __ldg(&g_csr[j + 2]), s3 = __ldg(&g_csr[j + 3]);
                float4 v0 = tp[s0], v1 = tp[s1], v2 = tp[s2], v3 = tp[s3];
                a0.x += v0.x; a0.y += v0.y; a0.z += v0.z; a0.w += v0.w;
                a1.x += v1.x; a1.y += v1.y; a1.z += v1.z; a1.w += v1.w;
                a2.x += v2.x; a2.y += v2.y; a2.z += v2.z; a2.w += v2.w;
                a3.x += v3.x; a3.y += v3.y; a3.z += v3.z; a3.w += v3.w;
            }
            for (; j < jend; j++) {
                float4 v = tp[__ldg(&g_csr[j])];
                a0.x += v.x; a0.y += v.y; a0.z += v.z; a0.w += v.w;
            }
            float dv = g_dinv[i];
            float h0 = tanhf(((a0.x + a1.x) + (a2.x + a3.x)) * dv + __ldg(&b2[0]));
            float h1 = tanhf(((a0.y + a1.y) + (a2.y + a3.y)) * dv + __ldg(&b2[1]));
            float h2 = tanhf(((a0.z + a1.z) + (a2.z + a3.z)) * dv + __ldg(&b2[2]));
            float h3 = tanhf(((a0.w + a1.w) + (a2.w + a3.w)) * dv + __ldg(&b2[3]));
            float2 o;
            o.x = (h0*__ldg(&W3[0]) + h1*__ldg(&W3[2]) + h2*__ldg(&W3[4]) + h3*__ldg(&W3[6])) * dv;
            o.y = (h0*__ldg(&W3[1]) + h1*__ldg(&W3[3]) + h2*__ldg(&W3[5]) + h3*__ldg(&W3[7])) * dv;
            *(float2*)(g_tmpC + (size_t)i * 2) = o;
        }
    }
    grid_barrier(nb);

    // ---- phase 8: pull layer 3 (tmpC) + classifier + outputs ----
    {
        const float2* tp = (const float2*)g_tmpC;
        for (int i = gid; i < n; i += T) {
            float2 a0 = tp[i];
            float2 a1 = make_float2(0.f, 0.f), a2 = a1, a3 = a1;
            int j = g_rowoff[i];
            int jend = j + __ldcg(&g_deg[i]);
            for (; j + 4 <= jend; j += 4) {
                int s0 = __ldg(&g_csr[j]),     s1 = __ldg(&g_csr[j + 1]);
                int s2 = __ldg(&g_csr[j + 2]), s3 = __ldg(&g_csr[j + 3]);
                float2 v0 = tp[s0], v1 = tp[s1], v2 = tp[s2], v3 = tp[s3];
                a0.x += v0.x; a0.y += v0.y;
                a1.x += v1.x; a1.y += v1.y;
                a2.x += v2.x; a2.y += v2.y;
                a3.x += v3.x; a3.y += v3.y;
            }
            for (; j < jend; j++) {
                float2 v = tp[__ldg(&g_csr[j])];
                a0.x += v.x; a0.y += v.y;
            }
            float dv = g_dinv[i];
            float h0 = tanhf(((a0.x + a1.x) + (a2.x + a3.x)) * dv + __ldg(&b3[0]));
            float h1 = tanhf(((a0.y + a1.y) + (a2.y + a3.y)) * dv + __ldg(&b3[1]));
            *(float2*)(hsec + (size_t)i * 2) = make_float2(h0, h1);
            #pragma unroll
            for (int j0 = 0; j0 < 16; j0 += 4) {
                float4 v;
                v.x = h0*__ldg(&Wc[j0+0]) + h1*__ldg(&Wc[16+j0+0]) + __ldg(&bc[j0+0]);
                v.y = h0*__ldg(&Wc[j0+1]) + h1*__ldg(&Wc[16+j0+1]) + __ldg(&bc[j0+1]);
                v.z = h0*__ldg(&Wc[j0+2]) + h1*__ldg(&Wc[16+j0+2]) + __ldg(&bc[j0+2]);
                v.w = h0*__ldg(&Wc[j0+3]) + h1*__ldg(&Wc[16+j0+3]) + __ldg(&bc[j0+3]);
                *(float4*)(out + (size_t)i * 16 + j0) = v;
            }
        }
    }
}

extern "C" void kernel_launch(void* const* d_in, const int* in_sizes, int n_in,
                              void* d_out, int out_size) {
    const float* x  = (const float*)d_in[0];
    const float* W1 = (const float*)d_in[1];
    const float* b1 = (const float*)d_in[2];
    const float* W2 = (const float*)d_in[3];
    const float* b2 = (const float*)d_in[4];
    const float* W3 = (const float*)d_in[5];
    const float* b3 = (const float*)d_in[6];
    const float* Wc = (const float*)d_in[7];
    const float* bc = (const float*)d_in[8];
    const int*   ei = (const int*)d_in[9];

    const int n = in_sizes[0] / 128;
    const int e = in_sizes[9] / 2;
    const int* src = ei;
    const int* dst = ei + e;

    // Co-residency-safe grid: exactly what the occupancy calculator guarantees.
    int dev = 0;
    cudaGetDevice(&dev);
    int sms = 0;
    cudaDeviceGetAttribute(&sms, cudaDevAttrMultiProcessorCount, dev);
    int bpm = 0;
    cudaOccupancyMaxActiveBlocksPerMultiprocessor(&bpm, gcn_mega_kernel, THREADS, 0);
    if (bpm < 1) bpm = 1;
    if (bpm > 2) bpm = 2;   // __launch_bounds__ minBlocksPerMultiprocessor = 2
    int nb = sms * bpm;
    if (nb > NB_MAX) nb = NB_MAX;

    float* out  = (float*)d_out;
    float* hsec = out + (size_t)n * 16;

    gcn_mega_kernel<<<nb, THREADS>>>(x, W1, b1, W2, b2, W3, b3, Wc, bc,
                                     src, dst, out, hsec, n, e, nb);
}

// round 7
// speedup vs baseline: 1.0855x; 1.0855x over previous
#include <cuda_runtime.h>
#include <cstdint>

#define NMAX 200000
#define EMAX 6400000
#define NB_MAX 2368
#define BT 256          // build kernel block size
#define SIDX_CAP 11776  // 46KB smem staging for CSR slices
#define GT 64           // gemm tile nodes

// Scratch (device globals — no allocation allowed)
__device__ int g_deg[NMAX];
__device__ int g_rowoff[NMAX];
__device__ int g_cursor[NMAX];
__device__ int g_csum[NB_MAX];
__device__ int g_csr[EMAX];
__device__ __align__(16) float g_dinv[NMAX];
__device__ __align__(16) float g_tmpA[NMAX * 4];
__device__ __align__(16) float g_tmpB[NMAX * 4];
__device__ __align__(16) float g_tmpC[NMAX * 2];

// Monotonic ticket barrier — replay-safe (counters only grow; each round
// consumes exactly nb arrivals so alignment holds across graph replays).
__device__ unsigned int g_bar_arrive;
__device__ unsigned int g_bar_release;

__device__ __forceinline__ void grid_barrier(int nb) {
    __syncthreads();
    if (threadIdx.x == 0) {
        __threadfence();
        unsigned int ticket = atomicAdd(&g_bar_arrive, 1u);
        unsigned int target = ticket - (ticket % (unsigned)nb) + (unsigned)nb;
        if ((ticket % (unsigned)nb) == (unsigned)(nb - 1)) {
            atomicAdd(&g_bar_release, (unsigned)nb);
        } else {
            while (atomicAdd(&g_bar_release, 0u) < target) __nanosleep(64);
        }
    }
    __syncthreads();
    __threadfence();
}

static inline int cdiv(int a, int b) { return (a + b - 1) / b; }

// =================== persistent BUILD kernel (phases 0-4) ===================
__global__ void __launch_bounds__(BT)
build_kernel(const int* __restrict__ src, const int* __restrict__ dst,
             int n, int e, int nb) {
    __shared__ int wsum[BT / 32], woff[BT / 32];
    __shared__ int red[BT];

    const int t   = threadIdx.x;
    const int blk = blockIdx.x;
    const int gid = blk * BT + t;
    const int T   = nb * BT;

    // phase 0: zero degree
    for (int i = gid; i < n; i += T) __stcg(&g_deg[i], 0);
    grid_barrier(nb);

    // phase 1: count in-degree (RED, fire-and-forget)
    {
        int quads = e >> 2;
        for (int q = gid; q < quads; q += T) {
            int4 d4 = __ldg((const int4*)dst + q);
            atomicAdd(&g_deg[d4.x], 1);
            atomicAdd(&g_deg[d4.y], 1);
            atomicAdd(&g_deg[d4.z], 1);
            atomicAdd(&g_deg[d4.w], 1);
        }
        if (gid == 0)
            for (int i = quads * 4; i < e; i++) atomicAdd(&g_deg[dst[i]], 1);
    }
    grid_barrier(nb);

    // phase 2: block-local exclusive scan over this block's node chunk
    const int chunk = (n + nb - 1) / nb;
    const int c0 = min(n, blk * chunk);
    const int c1 = min(n, c0 + chunk);
    const int per = (chunk + BT - 1) / BT;
    const int r0 = min(c1, c0 + t * per);
    const int r1 = min(c1, r0 + per);
    {
        int s = 0;
        for (int i = r0; i < r1; i++) s += __ldcg(&g_deg[i]);
        int lane = t & 31, wid = t >> 5;
        int incl = s;
        #pragma unroll
        for (int off = 1; off < 32; off <<= 1) {
            int v = __shfl_up_sync(0xffffffffu, incl, off);
            if (lane >= off) incl += v;
        }
        if (lane == 31) wsum[wid] = incl;
        __syncthreads();
        if (t < BT / 32) {
            int acc = 0;
            for (int w = 0; w < t; w++) acc += wsum[w];
            woff[t] = acc;
        }
        __syncthreads();
        int run = incl - s + woff[wid];
        for (int i = r0; i < r1; i++) {
            g_rowoff[i] = run;
            run += __ldcg(&g_deg[i]);
        }
        if (t == 0) __stcg(&g_csum[blk], woff[BT / 32 - 1] + wsum[BT / 32 - 1]);
        __syncthreads();
    }
    grid_barrier(nb);

    // phase 3: apply chunk offsets + dinv + cursor
    {
        int p = 0;
        for (int j = t; j < blk; j += BT) p += __ldcg(&g_csum[j]);
        red[t] = p;
        __syncthreads();
        for (int step = BT / 2; step > 0; step >>= 1) {
            if (t < step) red[t] += red[t + step];
            __syncthreads();
        }
        int off = red[0];
        __syncthreads();
        for (int i = r0; i < r1; i++) {
            int v = g_rowoff[i] + off;
            g_rowoff[i] = v;
            g_cursor[i] = v;
            g_dinv[i] = rsqrtf((float)(__ldcg(&g_deg[i]) + 1));  // +1 self-loop
        }
    }
    grid_barrier(nb);

    // phase 4: CSR scatter
    {
        int quads = e >> 2;
        for (int q = gid; q < quads; q += T) {
            int4 s4 = __ldg((const int4*)src + q);
            int4 d4 = __ldg((const int4*)dst + q);
            int p;
            p = atomicAdd(&g_cursor[d4.x], 1); __stcg(&g_csr[p], s4.x);
            p = atomicAdd(&g_cursor[d4.y], 1); __stcg(&g_csr[p], s4.y);
            p = atomicAdd(&g_cursor[d4.z], 1); __stcg(&g_csr[p], s4.z);
            p = atomicAdd(&g_cursor[d4.w], 1); __stcg(&g_csr[p], s4.w);
        }
        if (gid == 0)
            for (int i = quads * 4; i < e; i++) {
                int p = atomicAdd(&g_cursor[dst[i]], 1);
                __stcg(&g_csr[p], src[i]);
            }
    }
}

// =================== layer-1 GEMM: tmpA = (x @ W1) * dinv ===================
__global__ void gemm1_kernel(const float* __restrict__ x, const float* __restrict__ W, int n) {
    __shared__ float4 Wv[128];
    __shared__ float4 xs[GT * 33];
    __shared__ float4 ps[GT];
    int t = threadIdx.x;              // 128 threads
    if (t < 128) Wv[t] = ((const float4*)W)[t];
    int node0 = blockIdx.x * GT;
    int nn = min(GT, n - node0);
    int tot = nn * 32;
    const float4* x4 = (const float4*)x;
    for (int idx = t; idx < tot; idx += 128) {
        int nd = idx >> 5, kq = idx & 31;
        xs[nd * 33 + kq] = x4[(size_t)(node0 + nd) * 32 + kq];
    }
    __syncthreads();
    int half = t >> 6;
    int node = t & 63;
    float4 acc = make_float4(0.f, 0.f, 0.f, 0.f);
    if (node < nn) {
        int k0 = half * 16;
        #pragma unroll
        for (int kq = 0; kq < 16; kq++) {
            float4 xv = xs[node * 33 + k0 + kq];
            float4 w0 = Wv[(k0 + kq) * 4 + 0];
            float4 w1 = Wv[(k0 + kq) * 4 + 1];
            float4 w2 = Wv[(k0 + kq) * 4 + 2];
            float4 w3 = Wv[(k0 + kq) * 4 + 3];
            acc.x += xv.x * w0.x + xv.y * w1.x + xv.z * w2.x + xv.w * w3.x;
            acc.y += xv.x * w0.y + xv.y * w1.y + xv.z * w2.y + xv.w * w3.y;
            acc.z += xv.x * w0.z + xv.y * w1.z + xv.z * w2.z + xv.w * w3.z;
            acc.w += xv.x * w0.w + xv.y * w1.w + xv.z * w2.w + xv.w * w3.w;
        }
    }
    if (half == 1) ps[node] = acc;
    __syncthreads();
    if (half == 0 && node < nn) {
        float4 b = ps[node];
        int i = node0 + node;
        float dv = g_dinv[i];
        float4 o = make_float4((acc.x + b.x) * dv, (acc.y + b.y) * dv,
                               (acc.z + b.z) * dv, (acc.w + b.w) * dv);
        *(float4*)(g_tmpA + (size_t)i * 4) = o;
    }
}

// ========= fused pull (FIN=4): aggregate + tanh + next GEMM + prescale =========
template <int FNEXT>
__global__ void pull4_kernel(const float* __restrict__ tin,
                             const float* __restrict__ b,
                             const float* __restrict__ Wn,
                             float* __restrict__ tout, int n) {
    __shared__ int sidx[SIDX_CAP];
    int node0 = blockIdx.x * 256;
    int t = threadIdx.x;
    int nn = min(256, n - node0);
    int lastn = node0 + nn - 1;
    int base = g_rowoff[node0];
    int cnt = g_rowoff[lastn] + g_deg[lastn] - base;
    bool insm = (cnt <= SIDX_CAP);
    if (insm)
        for (int j = t; j < cnt; j += 256) sidx[j] = g_csr[base + j];
    __syncthreads();

    int i = node0 + t;
    if (i >= n) return;
    const float4* tp = (const float4*)tin;
    float4 a0 = tp[i];  // self-loop term
    float4 a1 = make_float4(0.f, 0.f, 0.f, 0.f), a2 = a1, a3 = a1;
    int cntl = g_deg[i];
    if (insm) {
        int j = g_rowoff[i] - base, jend = j + cntl;
        for (; j + 4 <= jend; j += 4) {
            float4 v0 = tp[sidx[j]], v1 = tp[sidx[j + 1]], v2 = tp[sidx[j + 2]], v3 = tp[sidx[j + 3]];
            a0.x += v0.x; a0.y += v0.y; a0.z += v0.z; a0.w += v0.w;
            a1.x += v1.x; a1.y += v1.y; a1.z += v1.z; a1.w += v1.w;
            a2.x += v2.x; a2.y += v2.y; a2.z += v2.z; a2.w += v2.w;
            a3.x += v3.x; a3.y += v3.y; a3.z += v3.z; a3.w += v3.w;
        }
        for (; j < jend; j++) {
            float4 v = tp[sidx[j]];
            a0.x += v.x; a0.y += v.y; a0.z += v.z; a0.w += v.w;
        }
    } else {
        int j = g_rowoff[i], jend = j + cntl;
        for (; j + 4 <= jend; j += 4) {
            float4 v0 = tp[g_csr[j]], v1 = tp[g_csr[j + 1]], v2 = tp[g_csr[j + 2]], v3 = tp[g_csr[j + 3]];
            a0.x += v0.x; a0.y += v0.y; a0.z += v0.z; a0.w += v0.w;
            a1.x += v1.x; a1.y += v1.y; a1.z += v1.z; a1.w += v1.w;
            a2.x += v2.x; a2.y += v2.y; a2.z += v2.z; a2.w += v2.w;
            a3.x += v3.x; a3.y += v3.y; a3.z += v3.z; a3.w += v3.w;
        }
        for (; j < jend; j++) {
            float4 v = tp[g_csr[j]];
            a0.x += v.x; a0.y += v.y; a0.z += v.z; a0.w += v.w;
        }
    }
    float dv = g_dinv[i];
    float sx = (a0.x + a1.x) + (a2.x + a3.x);
    float sy = (a0.y + a1.y) + (a2.y + a3.y);
    float sz = (a0.z + a1.z) + (a2.z + a3.z);
    float sw = (a0.w + a1.w) + (a2.w + a3.w);
    float h0 = tanhf(sx * dv + __ldg(&b[0]));
    float h1 = tanhf(sy * dv + __ldg(&b[1]));
    float h2 = tanhf(sz * dv + __ldg(&b[2]));
    float h3 = tanhf(sw * dv + __ldg(&b[3]));
    if (FNEXT == 4) {
        float4 o;
        o.x = (h0*__ldg(&Wn[0*4+0]) + h1*__ldg(&Wn[1*4+0]) + h2*__ldg(&Wn[2*4+0]) + h3*__ldg(&Wn[3*4+0])) * dv;
        o.y = (h0*__ldg(&Wn[0*4+1]) + h1*__ldg(&Wn[1*4+1]) + h2*__ldg(&Wn[2*4+1]) + h3*__ldg(&Wn[3*4+1])) * dv;
        o.z = (h0*__ldg(&Wn[0*4+2]) + h1*__ldg(&Wn[1*4+2]) + h2*__ldg(&Wn[2*4+2]) + h3*__ldg(&Wn[3*4+2])) * dv;
        o.w = (h0*__ldg(&Wn[0*4+3]) + h1*__ldg(&Wn[1*4+3]) + h2*__ldg(&Wn[2*4+3]) + h3*__ldg(&Wn[3*4+3])) * dv;
        *(float4*)(tout + (size_t)i * 4) = o;
    } else {
        float2 o;
        o.x = (h0*__ldg(&Wn[0*2+0]) + h1*__ldg(&Wn[1*2+0]) + h2*__ldg(&Wn[2*2+0]) + h3*__ldg(&Wn[3*2+0])) * dv;
        o.y = (h0*__ldg(&Wn[0*2+1]) + h1*__ldg(&Wn[1*2+1]) + h2*__ldg(&Wn[2*2+1]) + h3*__ldg(&Wn[3*2+1])) * dv;
        *(float2*)(tout + (size_t)i * 2) = o;
    }
}

// ========= fused pull (FIN=2) + classifier + outputs =========
__global__ void pull2_cls_kernel(const float* __restrict__ tin,
                                 const float* __restrict__ b3,
                                 const float* __restrict__ Wc,
                                 const float* __restrict__ bc,
                                 float* __restrict__ out,
                                 float* __restrict__ hsec, int n) {
    __shared__ int sidx[SIDX_CAP];
    int node0 = blockIdx.x * 256;
    int t = threadIdx.x;
    int nn = min(256, n - node0);
    int lastn = node0 + nn - 1;
    int base = g_rowoff[node0];
    int cnt = g_rowoff[lastn] + g_deg[lastn] - base;
    bool insm = (cnt <= SIDX_CAP);
    if (insm)
        for (int j = t; j < cnt; j += 256) sidx[j] = g_csr[base + j];
    __syncthreads();

    int i = node0 + t;
    if (i >= n) return;
    const float2* tp = (const float2*)tin;
    float2 a0 = tp[i];
    float2 a1 = make_float2(0.f, 0.f), a2 = a1, a3 = a1;
    int cntl = g_deg[i];
    if (insm) {
        int j = g_rowoff[i] - base, jend = j + cntl;
        for (; j + 4 <= jend; j += 4) {
            float2 v0 = tp[sidx[j]], v1 = tp[sidx[j + 1]], v2 = tp[sidx[j + 2]], v3 = tp[sidx[j + 3]];
            a0.x += v0.x; a0.y += v0.y;
            a1.x += v1.x; a1.y += v1.y;
            a2.x += v2.x; a2.y += v2.y;
            a3.x += v3.x; a3.y += v3.y;
        }
        for (; j < jend; j++) { float2 v = tp[sidx[j]]; a0.x += v.x; a0.y += v.y; }
    } else {
        int j = g_rowoff[i], jend = j + cntl;
        for (; j < jend; j++) { float2 v = tp[g_csr[j]]; a0.x += v.x; a0.y += v.y; }
    }
    float dv = g_dinv[i];
    float sx = (a0.x + a1.x) + (a2.x + a3.x);
    float sy = (a0.y + a1.y) + (a2.y + a3.y);
    float h0 = tanhf(sx * dv + __ldg(&b3[0]));
    float h1 = tanhf(sy * dv + __ldg(&b3[1]));
    *(float2*)(hsec + (size_t)i * 2) = make_float2(h0, h1);
    #pragma unroll
    for (int j0 = 0; j0 < 16; j0 += 4) {
        float4 v;
        v.x = h0*__ldg(&Wc[0*16+j0+0]) + h1*__ldg(&Wc[1*16+j0+0]) + __ldg(&bc[j0+0]);
        v.y = h0*__ldg(&Wc[0*16+j0+1]) + h1*__ldg(&Wc[1*16+j0+1]) + __ldg(&bc[j0+1]);
        v.z = h0*__ldg(&Wc[0*16+j0+2]) + h1*__ldg(&Wc[1*16+j0+2]) + __ldg(&bc[j0+2]);
        v.w = h0*__ldg(&Wc[0*16+j0+3]) + h1*__ldg(&Wc[1*16+j0+3]) + __ldg(&bc[j0+3]);
        *(float4*)(out + (size_t)i * 16 + j0) = v;
    }
}

extern "C" void kernel_launch(void* const* d_in, const int* in_sizes, int n_in,
                              void* d_out, int out_size) {
    const float* x  = (const float*)d_in[0];
    const float* W1 = (const float*)d_in[1];
    const float* b1 = (const float*)d_in[2];
    const float* W2 = (const float*)d_in[3];
    const float* b2 = (const float*)d_in[4];
    const float* W3 = (const float*)d_in[5];
    const float* b3 = (const float*)d_in[6];
    const float* Wc = (const float*)d_in[7];
    const float* bc = (const float*)d_in[8];
    const int*   ei = (const int*)d_in[9];

    const int n = in_sizes[0] / 128;
    const int e = in_sizes[9] / 2;
    const int* src = ei;
    const int* dst = ei + e;

    // Co-residency-safe grid for the persistent build kernel.
    int dev = 0;
    cudaGetDevice(&dev);
    int sms = 0;
    cudaDeviceGetAttribute(&sms, cudaDevAttrMultiProcessorCount, dev);
    int bpm = 0;
    cudaOccupancyMaxActiveBlocksPerMultiprocessor(&bpm, build_kernel, BT, 0);
    if (bpm < 1) bpm = 1;
    int nb = sms * bpm;
    if (nb > NB_MAX) nb = NB_MAX;

    float* tmpA; cudaGetSymbolAddress((void**)&tmpA, g_tmpA);
    float* tmpB; cudaGetSymbolAddress((void**)&tmpB, g_tmpB);
    float* tmpC; cudaGetSymbolAddress((void**)&tmpC, g_tmpC);

    // 1 launch: full CSR + normalization build
    build_kernel<<<nb, BT>>>(src, dst, n, e, nb);

    // heavy phases at full occupancy
    gemm1_kernel<<<cdiv(n, GT), 128>>>(x, W1, n);
    pull4_kernel<4><<<cdiv(n, 256), 256>>>(tmpA, b1, W2, tmpB, n);
    pull4_kernel<2><<<cdiv(n, 256), 256>>>(tmpB, b2, W3, tmpC, n);

    float* out  = (float*)d_out;
    float* hsec = out + (size_t)n * 16;
    pull2_cls_kernel<<<cdiv(n, 256), 256>>>(tmpC, b3, Wc, bc, out, hsec, n);
}

// round 8
// speedup vs baseline: 1.2024x; 1.1076x over previous
#include <cuda_runtime.h>
#include <cstdint>

#define NMAX 200000
#define EMAX 6400000
#define CHUNK 8192
#define NCHUNKS ((NMAX + CHUNK - 1) / CHUNK)   // 25
#define GT 64   // gemm tile nodes

// Scratch (device globals — no allocation allowed)
__device__ int g_deg[NMAX];
__device__ int g_rowoff[NMAX];
__device__ int g_cursor[NMAX];
__device__ int g_csum[NCHUNKS];
__device__ int g_csr[EMAX];
__device__ __align__(16) float g_dinv[NMAX];
__device__ __align__(16) float g_tmpA[NMAX * 4];
__device__ __align__(16) float g_tmpB[NMAX * 4];
__device__ __align__(16) float g_tmpC[NMAX * 2];

static inline int cdiv(int a, int b) { return (a + b - 1) / b; }

// ---------------- build kernels (R4 structure — measured fastest) ----------------
__global__ void zero_deg_kernel(int n) {
    int i = blockIdx.x * blockDim.x + threadIdx.x;
    if (i < n) g_deg[i] = 0;
}

__global__ void count_deg_kernel(const int* __restrict__ dst, int e) {
    int t = blockIdx.x * blockDim.x + threadIdx.x;
    int base = t * 4;
    if (base >= e) return;
    if (base + 4 <= e) {
        int4 d4 = *(const int4*)(dst + base);
        atomicAdd(&g_deg[d4.x], 1);
        atomicAdd(&g_deg[d4.y], 1);
        atomicAdd(&g_deg[d4.z], 1);
        atomicAdd(&g_deg[d4.w], 1);
    } else {
        for (int i = base; i < e; i++) atomicAdd(&g_deg[dst[i]], 1);
    }
}
__global__ void count_deg_scalar_kernel(const int* __restrict__ dst, int e) {
    int i = blockIdx.x * blockDim.x + threadIdx.x;
    if (i < e) atomicAdd(&g_deg[dst[i]], 1);
}

__global__ void scanA_kernel(int n) {
    int t = threadIdx.x;                       // 256 threads, 32 nodes each
    int base = blockIdx.x * CHUNK + t * 32;
    int s = 0;
    for (int r = 0; r < 32; r++) {
        int node = base + r;
        if (node < n) s += g_deg[node];
    }
    int lane = t & 31, wid = t >> 5;
    int incl = s;
    #pragma unroll
    for (int off = 1; off < 32; off <<= 1) {
        int v = __shfl_up_sync(0xffffffffu, incl, off);
        if (lane >= off) incl += v;
    }
    __shared__ int wsum[8], woff[8];
    if (lane == 31) wsum[wid] = incl;
    __syncthreads();
    if (t < 8) {
        int acc = 0;
        for (int w = 0; w < t; w++) acc += wsum[w];
        woff[t] = acc;
    }
    __syncthreads();
    int run = incl - s + woff[wid];
    for (int r = 0; r < 32; r++) {
        int node = base + r;
        if (node < n) { g_rowoff[node] = run; run += g_deg[node]; }
    }
    if (t == 255) g_csum[blockIdx.x] = incl + woff[wid];
}

__global__ void scanB_kernel(int nb) {         // nb <= 32
    int t = threadIdx.x;
    int v = (t < nb) ? g_csum[t] : 0;
    int incl = v;
    #pragma unroll
    for (int off = 1; off < 32; off <<= 1) {
        int u = __shfl_up_sync(0xffffffffu, incl, off);
        if (t >= off) incl += u;
    }
    if (t < nb) g_csum[t] = incl - v;
}

__global__ void scanC_kernel(int n) {
    int i = blockIdx.x * blockDim.x + threadIdx.x;
    if (i >= n) return;
    int off = g_rowoff[i] + g_csum[i / CHUNK];
    g_rowoff[i] = off;
    g_cursor[i] = off;
    g_dinv[i] = rsqrtf((float)(g_deg[i] + 1)); // +1 self-loop
}

__global__ void scatter_kernel(const int* __restrict__ src, const int* __restrict__ dst, int e) {
    int t = blockIdx.x * blockDim.x + threadIdx.x;
    int base = t * 4;
    if (base >= e) return;
    if (base + 4 <= e) {
        int4 s4 = *(const int4*)(src + base);
        int4 d4 = *(const int4*)(dst + base);
        int p;
        p = atomicAdd(&g_cursor[d4.x], 1); g_csr[p] = s4.x;
        p = atomicAdd(&g_cursor[d4.y], 1); g_csr[p] = s4.y;
        p = atomicAdd(&g_cursor[d4.z], 1); g_csr[p] = s4.z;
        p = atomicAdd(&g_cursor[d4.w], 1); g_csr[p] = s4.w;
    } else {
        for (int i = base; i < e; i++) {
            int p = atomicAdd(&g_cursor[dst[i]], 1);
            g_csr[p] = src[i];
        }
    }
}
__global__ void scatter_scalar_kernel(const int* __restrict__ src, const int* __restrict__ dst, int e) {
    int i = blockIdx.x * blockDim.x + threadIdx.x;
    if (i >= e) return;
    int p = atomicAdd(&g_cursor[dst[i]], 1);
    g_csr[p] = src[i];
}

// ---------------- layer-1 GEMM: tmpA = (x @ W1) * dinv ----------------
__global__ void gemm1_kernel(const float* __restrict__ x, const float* __restrict__ W, int n) {
    __shared__ float4 Wv[128];
    __shared__ float4 xs[GT * 33];
    __shared__ float4 ps[GT];
    int t = threadIdx.x;              // 128 threads
    if (t < 128) Wv[t] = ((const float4*)W)[t];
    int node0 = blockIdx.x * GT;
    int nn = min(GT, n - node0);
    int tot = nn * 32;
    const float4* x4 = (const float4*)x;
    for (int idx = t; idx < tot; idx += 128) {
        int nd = idx >> 5, kq = idx & 31;
        xs[nd * 33 + kq] = x4[(size_t)(node0 + nd) * 32 + kq];
    }
    __syncthreads();
    int half = t >> 6;
    int node = t & 63;
    float4 acc = make_float4(0.f, 0.f, 0.f, 0.f);
    if (node < nn) {
        int k0 = half * 16;
        #pragma unroll
        for (int kq = 0; kq < 16; kq++) {
            float4 xv = xs[node * 33 + k0 + kq];
            float4 w0 = Wv[(k0 + kq) * 4 + 0];
            float4 w1 = Wv[(k0 + kq) * 4 + 1];
            float4 w2 = Wv[(k0 + kq) * 4 + 2];
            float4 w3 = Wv[(k0 + kq) * 4 + 3];
            acc.x += xv.x * w0.x + xv.y * w1.x + xv.z * w2.x + xv.w * w3.x;
            acc.y += xv.x * w0.y + xv.y * w1.y + xv.z * w2.y + xv.w * w3.y;
            acc.z += xv.x * w0.z + xv.y * w1.z + xv.z * w2.z + xv.w * w3.z;
            acc.w += xv.x * w0.w + xv.y * w1.w + xv.z * w2.w + xv.w * w3.w;
        }
    }
    if (half == 1) ps[node] = acc;
    __syncthreads();
    if (half == 0 && node < nn) {
        float4 b = ps[node];
        int i = node0 + node;
        float dv = g_dinv[i];
        float4 o = make_float4((acc.x + b.x) * dv, (acc.y + b.y) * dv,
                               (acc.z + b.z) * dv, (acc.w + b.w) * dv);
        *(float4*)(g_tmpA + (size_t)i * 4) = o;
    }
}

// ========= fused pull (FIN=4): no smem staging, high occupancy =========
template <int FNEXT>
__global__ void __launch_bounds__(256, 6)
pull4_kernel(const float* __restrict__ tin,
             const float* __restrict__ b,
             const float* __restrict__ Wn,
             float* __restrict__ tout, int n) {
    int i = blockIdx.x * blockDim.x + threadIdx.x;
    if (i >= n) return;
    const float4* tp = (const float4*)tin;
    float4 a0 = tp[i];  // self-loop term (prescaled)
    float4 a1 = make_float4(0.f, 0.f, 0.f, 0.f), a2 = a1, a3 = a1;
    int j = g_rowoff[i];
    int jend = j + g_deg[i];
    for (; j + 4 <= jend; j += 4) {
        int s0 = __ldg(&g_csr[j]),     s1 = __ldg(&g_csr[j + 1]);
        int s2 = __ldg(&g_csr[j + 2]), s3 = __ldg(&g_csr[j + 3]);
        float4 v0 = tp[s0], v1 = tp[s1], v2 = tp[s2], v3 = tp[s3];
        a0.x += v0.x; a0.y += v0.y; a0.z += v0.z; a0.w += v0.w;
        a1.x += v1.x; a1.y += v1.y; a1.z += v1.z; a1.w += v1.w;
        a2.x += v2.x; a2.y += v2.y; a2.z += v2.z; a2.w += v2.w;
        a3.x += v3.x; a3.y += v3.y; a3.z += v3.z; a3.w += v3.w;
    }
    for (; j < jend; j++) {
        float4 v = tp[__ldg(&g_csr[j])];
        a0.x += v.x; a0.y += v.y; a0.z += v.z; a0.w += v.w;
    }
    float dv = g_dinv[i];
    float sx = (a0.x + a1.x) + (a2.x + a3.x);
    float sy = (a0.y + a1.y) + (a2.y + a3.y);
    float sz = (a0.z + a1.z) + (a2.z + a3.z);
    float sw = (a0.w + a1.w) + (a2.w + a3.w);
    float h0 = tanhf(sx * dv + __ldg(&b[0]));
    float h1 = tanhf(sy * dv + __ldg(&b[1]));
    float h2 = tanhf(sz * dv + __ldg(&b[2]));
    float h3 = tanhf(sw * dv + __ldg(&b[3]));
    if (FNEXT == 4) {
        float4 o;
        o.x = (h0*__ldg(&Wn[0*4+0]) + h1*__ldg(&Wn[1*4+0]) + h2*__ldg(&Wn[2*4+0]) + h3*__ldg(&Wn[3*4+0])) * dv;
        o.y = (h0*__ldg(&Wn[0*4+1]) + h1*__ldg(&Wn[1*4+1]) + h2*__ldg(&Wn[2*4+1]) + h3*__ldg(&Wn[3*4+1])) * dv;
        o.z = (h0*__ldg(&Wn[0*4+2]) + h1*__ldg(&Wn[1*4+2]) + h2*__ldg(&Wn[2*4+2]) + h3*__ldg(&Wn[3*4+2])) * dv;
        o.w = (h0*__ldg(&Wn[0*4+3]) + h1*__ldg(&Wn[1*4+3]) + h2*__ldg(&Wn[2*4+3]) + h3*__ldg(&Wn[3*4+3])) * dv;
        *(float4*)(tout + (size_t)i * 4) = o;
    } else {
        float2 o;
        o.x = (h0*__ldg(&Wn[0*2+0]) + h1*__ldg(&Wn[1*2+0]) + h2*__ldg(&Wn[2*2+0]) + h3*__ldg(&Wn[3*2+0])) * dv;
        o.y = (h0*__ldg(&Wn[0*2+1]) + h1*__ldg(&Wn[1*2+1]) + h2*__ldg(&Wn[2*2+1]) + h3*__ldg(&Wn[3*2+1])) * dv;
        *(float2*)(tout + (size_t)i * 2) = o;
    }
}

// ========= fused pull (FIN=2) + classifier + outputs =========
__global__ void __launch_bounds__(256, 6)
pull2_cls_kernel(const float* __restrict__ tin,
                 const float* __restrict__ b3,
                 const float* __restrict__ Wc,
                 const float* __restrict__ bc,
                 float* __restrict__ out,
                 float* __restrict__ hsec, int n) {
    int i = blockIdx.x * blockDim.x + threadIdx.x;
    if (i >= n) return;
    const float2* tp = (const float2*)tin;
    float2 a0 = tp[i];
    float2 a1 = make_float2(0.f, 0.f), a2 = a1, a3 = a1;
    int j = g_rowoff[i];
    int jend = j + g_deg[i];
    for (; j + 4 <= jend; j += 4) {
        int s0 = __ldg(&g_csr[j]),     s1 = __ldg(&g_csr[j + 1]);
        int s2 = __ldg(&g_csr[j + 2]), s3 = __ldg(&g_csr[j + 3]);
        float2 v0 = tp[s0], v1 = tp[s1], v2 = tp[s2], v3 = tp[s3];
        a0.x += v0.x; a0.y += v0.y;
        a1.x += v1.x; a1.y += v1.y;
        a2.x += v2.x; a2.y += v2.y;
        a3.x += v3.x; a3.y += v3.y;
    }
    for (; j < jend; j++) {
        float2 v = tp[__ldg(&g_csr[j])];
        a0.x += v.x; a0.y += v.y;
    }
    float dv = g_dinv[i];
    float sx = (a0.x + a1.x) + (a2.x + a3.x);
    float sy = (a0.y + a1.y) + (a2.y + a3.y);
    float h0 = tanhf(sx * dv + __ldg(&b3[0]));
    float h1 = tanhf(sy * dv + __ldg(&b3[1]));
    *(float2*)(hsec + (size_t)i * 2) = make_float2(h0, h1);
    #pragma unroll
    for (int j0 = 0; j0 < 16; j0 += 4) {
        float4 v;
        v.x = h0*__ldg(&Wc[0*16+j0+0]) + h1*__ldg(&Wc[1*16+j0+0]) + __ldg(&bc[j0+0]);
        v.y = h0*__ldg(&Wc[0*16+j0+1]) + h1*__ldg(&Wc[1*16+j0+1]) + __ldg(&bc[j0+1]);
        v.z = h0*__ldg(&Wc[0*16+j0+2]) + h1*__ldg(&Wc[1*16+j0+2]) + __ldg(&bc[j0+2]);
        v.w = h0*__ldg(&Wc[0*16+j0+3]) + h1*__ldg(&Wc[1*16+j0+3]) + __ldg(&bc[j0+3]);
        *(float4*)(out + (size_t)i * 16 + j0) = v;
    }
}

extern "C" void kernel_launch(void* const* d_in, const int* in_sizes, int n_in,
                              void* d_out, int out_size) {
    const float* x  = (const float*)d_in[0];
    const float* W1 = (const float*)d_in[1];
    const float* b1 = (const float*)d_in[2];
    const float* W2 = (const float*)d_in[3];
    const float* b2 = (const float*)d_in[4];
    const float* W3 = (const float*)d_in[5];
    const float* b3 = (const float*)d_in[6];
    const float* Wc = (const float*)d_in[7];
    const float* bc = (const float*)d_in[8];
    const int*   ei = (const int*)d_in[9];

    const int n = in_sizes[0] / 128;
    const int e = in_sizes[9] / 2;
    const int* src = ei;
    const int* dst = ei + e;

    const int B = 256;
    const bool vec = ((e & 3) == 0) &&
                     ((((unsigned long long)(uintptr_t)dst) & 15ull) == 0) &&
                     ((((unsigned long long)(uintptr_t)src) & 15ull) == 0);

    float* tmpA; cudaGetSymbolAddress((void**)&tmpA, g_tmpA);
    float* tmpB; cudaGetSymbolAddress((void**)&tmpB, g_tmpB);
    float* tmpC; cudaGetSymbolAddress((void**)&tmpC, g_tmpC);

    // build normalization + CSR (R4 structure)
    zero_deg_kernel<<<cdiv(n, B), B>>>(n);
    if (vec) count_deg_kernel<<<cdiv(cdiv(e, 4), B), B>>>(dst, e);
    else     count_deg_scalar_kernel<<<cdiv(e, B), B>>>(dst, e);
    scanA_kernel<<<cdiv(n, CHUNK), 256>>>(n);
    scanB_kernel<<<1, 32>>>(cdiv(n, CHUNK));
    scanC_kernel<<<cdiv(n, B), B>>>(n);
    if (vec) scatter_kernel<<<cdiv(cdiv(e, 4), B), B>>>(src, dst, e);
    else     scatter_scalar_kernel<<<cdiv(e, B), B>>>(src, dst, e);

    // layer 1 GEMM (prescaled)
    gemm1_kernel<<<cdiv(n, GT), 128>>>(x, W1, n);

    // fused pull layers (no smem staging — high occupancy)
    pull4_kernel<4><<<cdiv(n, B), B>>>(tmpA, b1, W2, tmpB, n);
    pull4_kernel<2><<<cdiv(n, B), B>>>(tmpB, b2, W3, tmpC, n);

    float* out  = (float*)d_out;
    float* hsec = out + (size_t)n * 16;
    pull2_cls_kernel<<<cdiv(n, B), B>>>(tmpC, b3, Wc, bc, out, hsec, n);
}